// round 16
// baseline (speedup 1.0000x reference)
#include <cuda_runtime.h>
#include <cuda_fp16.h>
#include <math.h>

#define SEQ  4096
#define EMB  2048
#define NH   16
#define NKVH 4
#define HD   128
#define WIN  2048
#define QDIM (NH*HD)    /* 2048 */
#define KVDIM (NKVH*HD) /* 512  */

// -------- scratch (device globals; no allocations allowed) --------
__device__ float  g_q [SEQ * QDIM];
__device__ float  g_k [SEQ * KVDIM];
__device__ __half g_q16[SEQ*QDIM];
__device__ __half g_k16[SEQ*KVDIM];
__device__ __half g_v16[SEQ*KVDIM];
__device__ __half g_at16[SEQ*QDIM];
__device__ __half g_x16q[SEQ*EMB], g_x16k[SEQ*EMB], g_x16v[SEQ*EMB];
__device__ __half g_w16q[EMB*QDIM], g_w16k[EMB*KVDIM], g_w16v[EMB*KVDIM], g_w16o[QDIM*EMB];

// ---------------- PTX helpers ----------------
#define LDSM_X4(r0,r1,r2,r3,addr) \
  asm volatile("ldmatrix.sync.aligned.m8n8.x4.shared.b16 {%0,%1,%2,%3}, [%4];" \
    : "=r"(r0),"=r"(r1),"=r"(r2),"=r"(r3) : "r"(addr))

#define LDSM_X4_T(r0,r1,r2,r3,addr) \
  asm volatile("ldmatrix.sync.aligned.m8n8.x4.trans.shared.b16 {%0,%1,%2,%3}, [%4];" \
    : "=r"(r0),"=r"(r1),"=r"(r2),"=r"(r3) : "r"(addr))

#define MMA16816H(c, a0,a1,a2,a3, b0,b1) \
  asm volatile("mma.sync.aligned.m16n8k16.row.col.f32.f16.f16.f32 " \
    "{%0,%1,%2,%3}, {%4,%5,%6,%7}, {%8,%9}, {%0,%1,%2,%3};" \
    : "+f"((c)[0]),"+f"((c)[1]),"+f"((c)[2]),"+f"((c)[3]) \
    : "r"(a0),"r"(a1),"r"(a2),"r"(a3),"r"(b0),"r"(b1))

#define CP_ASYNC16(dst32, srcptr) \
  asm volatile("cp.async.cg.shared.global [%0], [%1], 16;" :: "r"(dst32), "l"(srcptr))
#define CP_COMMIT() asm volatile("cp.async.commit_group;")
#define CP_WAIT0()  asm volatile("cp.async.wait_group 0;")

__device__ __forceinline__ unsigned packh2(float a, float b) {
    __half2 h = __floats2half2_rn(a, b);
    return *(unsigned*)&h;
}

// =====================================================================
// merged pre-pass: quantize all 7 tensors to fp16 (1 launch)
// =====================================================================
struct QArg { const float4* s; uint2* d; int nblk; };
struct QPack { QArg a[7]; };

__global__ __launch_bounds__(256) void quant_all(QPack p)
{
    int b = blockIdx.x;
    int seg = 0;
#pragma unroll
    for (int i = 0; i < 7; i++) {
        if (b >= p.a[seg].nblk) { b -= p.a[seg].nblk; seg++; }
    }
    const QArg sa = p.a[seg];
    int i = b * 256 + threadIdx.x;
    float4 v = sa.s[i];
    sa.d[i] = make_uint2(packh2(v.x, v.y), packh2(v.z, v.w));
}

// =====================================================================
// fp16 GEMM v10 (unchanged): 1 MMA/product, BK=64, 2-stage, 2 CTAs/SM.
// =====================================================================
#define A9_STRIDE 72
#define B9_STRIDE 136
#define G9_A  0
#define G9_B  18432
#define G9_STAGE 35840
#define SMEM_G9 (2*G9_STAGE)

struct GArg {
    const __half *A, *B;
    float* C;
    __half* C16;
    int N;
};

__global__ __launch_bounds__(256, 2) void gemm10(
    GArg a0, GArg a1, GArg a2, int t0, int t1, int K)
{
    extern __shared__ char smg[];
    const unsigned smu = (unsigned)__cvta_generic_to_shared(smg);

    GArg ga; int bx = blockIdx.x, bn;
    if (bx < t0)      { ga = a0; bn = bx * 128; }
    else if (bx < t1) { ga = a1; bn = (bx - t0) * 128; }
    else              { ga = a2; bn = (bx - t1) * 128; }
    const int N  = ga.N;
    const int bm = blockIdx.y * 128;

    const int tid  = threadIdx.x;
    const int warp = tid >> 5;
    const int lane = tid & 31;
    const int wm   = warp >> 2;
    const int wn   = warp & 3;

    float acc[4][4][4];
#pragma unroll
    for (int i = 0; i < 4; i++)
#pragma unroll
        for (int j = 0; j < 4; j++)
#pragma unroll
            for (int r = 0; r < 4; r++) acc[i][j][r] = 0.f;

    auto issue = [&](int stage, int k0) {
        unsigned sb = smu + stage * G9_STAGE;
#pragma unroll
        for (int p = 0; p < 4; p++) {
            int idx = tid + p * 256;
            int row = idx >> 3, u = idx & 7;
            CP_ASYNC16(sb + G9_A + row*144 + u*16, ga.A + (size_t)(bm + row)*K + k0 + u*8);
        }
#pragma unroll
        for (int p = 0; p < 4; p++) {
            int idx = tid + p * 256;
            int row = idx >> 4, u = idx & 15;
            CP_ASYNC16(sb + G9_B + row*272 + u*16, ga.B + (size_t)(k0 + row)*N + bn + u*8);
        }
        CP_COMMIT();
    };

    issue(0, 0);

    const int a_lrow = wm*64 + (lane & 15);
    const int a_lcol = (lane >> 4) * 8;

    const int nch = K / 64;
    for (int j = 0; j < nch; j++) {
        CP_WAIT0();
        __syncthreads();
        if (j + 1 < nch) issue((j + 1) & 1, (j + 1) * 64);

        const unsigned sa = smu + (j & 1) * G9_STAGE;

#pragma unroll
        for (int ks = 0; ks < 64; ks += 16) {
            unsigned ah[4][4];
#pragma unroll
            for (int mi = 0; mi < 4; mi++) {
                unsigned off = 2u * ((unsigned)((a_lrow + mi*16) * A9_STRIDE + ks + a_lcol));
                LDSM_X4(ah[mi][0], ah[mi][1], ah[mi][2], ah[mi][3], sa + G9_A + off);
            }
            unsigned bh[4][2];
#pragma unroll
            for (int nb = 0; nb < 2; nb++) {
                unsigned off = 2u * ((unsigned)((ks + (lane & 15)) * B9_STRIDE
                                               + wn*32 + nb*16 + (lane >> 4) * 8));
                unsigned r0, r1, r2, r3;
                LDSM_X4_T(r0, r1, r2, r3, sa + G9_B + off);
                bh[2*nb][0] = r0; bh[2*nb][1] = r1;
                bh[2*nb+1][0] = r2; bh[2*nb+1][1] = r3;
            }
#pragma unroll
            for (int mi = 0; mi < 4; mi++) {
#pragma unroll
                for (int ni = 0; ni < 4; ni++) {
                    MMA16816H(acc[mi][ni], ah[mi][0],ah[mi][1],ah[mi][2],ah[mi][3],
                              bh[ni][0], bh[ni][1]);
                }
            }
        }
    }

    const int g = lane >> 2, q = lane & 3;
#pragma unroll
    for (int mi = 0; mi < 4; mi++) {
#pragma unroll
        for (int ni = 0; ni < 4; ni++) {
            int row = bm + wm*64 + mi*16 + g;
            int col = bn + wn*32 + ni*8 + q*2;
            if (ga.C) {
                *(float2*)&ga.C[(size_t)row * N + col]       = make_float2(acc[mi][ni][0], acc[mi][ni][1]);
                *(float2*)&ga.C[(size_t)(row + 8) * N + col] = make_float2(acc[mi][ni][2], acc[mi][ni][3]);
            }
            if (ga.C16) {
                *(unsigned*)&ga.C16[(size_t)row * N + col]       = packh2(acc[mi][ni][0], acc[mi][ni][1]);
                *(unsigned*)&ga.C16[(size_t)(row + 8) * N + col] = packh2(acc[mi][ni][2], acc[mi][ni][3]);
            }
        }
    }
}

// =====================================================================
// RoPE (unchanged)
// =====================================================================
__global__ __launch_bounds__(256) void rope3_kernel(
    const int* __restrict__ pos_w,
    const float* __restrict__ q, const float* __restrict__ k,
    __half* __restrict__ q16, __half* __restrict__ k16)
{
    const int s = blockIdx.x;
    const int tid = threadIdx.x;
    __shared__ float cs[64], sn[64];

    const float QSCALE = (float)(1.4426950408889634 * 0.08838834764831845);

    if (tid < 64) {
        bool is64 = (pos_w[1] == 0);
        int pi = is64 ? pos_w[2 * s] : pos_w[s];
        float p = (float)pi;
        float ex = (float)(2 * tid) / (float)HD;
        float inv = powf(10000.0f, -ex);
        float ang = p * inv;
        sincosf(ang, &sn[tid], &cs[tid]);
    }
    __syncthreads();

    for (int idx = tid; idx < NH * 64; idx += 256) {
        int h = idx >> 6, d = idx & 63;
        size_t base = (size_t)s * QDIM + h * HD;
        float x1 = q[base + d], x2 = q[base + d + 64];
        float c = cs[d], si = sn[d];
        q16[base + d]      = __float2half_rn((x1 * c - x2 * si) * QSCALE);
        q16[base + d + 64] = __float2half_rn((x2 * c + x1 * si) * QSCALE);
    }
    for (int idx = tid; idx < NKVH * 64; idx += 256) {
        int h = idx >> 6, d = idx & 63;
        size_t base = (size_t)s * KVDIM + h * HD;
        float x1 = k[base + d], x2 = k[base + d + 64];
        float c = cs[d], si = sn[d];
        k16[base + d]      = __float2half_rn(x1 * c - x2 * si);
        k16[base + d + 64] = __float2half_rn(x2 * c + x1 * si);
    }
}

// =====================================================================
// MMA flash attention v6: fp16, 1 MMA/product, K-block 128.
// Changes vs v5 (bit-identical numerics):
//  - Q fragments hoisted to registers (loaded once per CTA)
//  - ok0/ok1 removed (provably always 1)
//  - o-rescale skipped when running max unchanged (__all_sync)
// =====================================================================
#define SMQ    0
#define KVBUF0 32768
#define KVSZ   65536
#define OF_K   0
#define OF_V   32768
#define SMEM_ATTN6 163840

__device__ __forceinline__ int swz(int row, int col_b16) {
    return row * 256 + ((((col_b16 >> 3) ^ (row & 7)) << 4)) + ((col_b16 & 7) << 1);
}

__global__ __launch_bounds__(256) void attn_mma6(
    const __half* __restrict__ Q16, const __half* __restrict__ K16,
    const __half* __restrict__ V16, __half* __restrict__ O16)
{
    extern __shared__ char sm[];
    const unsigned smu = (unsigned)__cvta_generic_to_shared(sm);

    const int tid  = threadIdx.x;
    const int warp = tid >> 5;
    const int lane = tid & 31;
    const int g    = lane >> 2;
    const int qd   = lane & 3;
    const int qb   = blockIdx.x;
    const int h    = blockIdx.y;
    const int kvh  = h >> 2;
    const int i0   = qb * 128;

    const int kb_lo = max(0, qb - 16);
    const int kb_hi = qb;

    {
#pragma unroll
        for (int rep = 0; rep < 8; rep++) {
            int chunk = tid + rep * 256;
            int row = chunk >> 4, u = chunk & 15;
            unsigned dsto = row * 256 + (((u ^ (row & 7)) << 4));
            CP_ASYNC16(smu + SMQ + dsto, Q16 + (size_t)(i0 + row) * QDIM + h * HD + u * 8);
        }
#pragma unroll
        for (int rep = 0; rep < 8; rep++) {
            int chunk = tid + rep * 256;
            int row = chunk >> 4, u = chunk & 15;
            unsigned dsto = row * 256 + (((u ^ (row & 7)) << 4));
            size_t srco = (size_t)(kb_lo * 128 + row) * KVDIM + kvh * HD + u * 8;
            CP_ASYNC16(smu + KVBUF0 + OF_K + dsto, K16 + srco);
            CP_ASYNC16(smu + KVBUF0 + OF_V + dsto, V16 + srco);
        }
        CP_COMMIT();
    }

    float o[16][4];
#pragma unroll
    for (int i = 0; i < 16; i++)
#pragma unroll
        for (int c = 0; c < 4; c++) o[i][c] = 0.f;

    float m0 = -1e30f, m1 = -1e30f, l0s = 0.f, l1s = 0.f;

    const int ig0 = i0 + warp * 16 + g;
    const int ig1 = ig0 + 8;

    // ---- peel: wait for Q + first KV, hoist Q fragments ----
    CP_WAIT0();
    __syncthreads();

    unsigned qf[8][4];
#pragma unroll
    for (int kc = 0; kc < 8; kc++) {
        int aoff = swz(warp*16 + (lane & 15), kc*16 + (lane >> 4) * 8);
        LDSM_X4(qf[kc][0], qf[kc][1], qf[kc][2], qf[kc][3], smu + SMQ + aoff);
    }

    for (int kb = kb_lo; kb <= kb_hi; kb++) {
        if (kb > kb_lo) {
            CP_WAIT0();
            __syncthreads();
        }

        const int buf = (kb - kb_lo) & 1;
        const unsigned kvb = smu + KVBUF0 + buf * KVSZ;

        if (kb + 1 <= kb_hi) {
            const unsigned nb = smu + KVBUF0 + (buf ^ 1) * KVSZ;
#pragma unroll
            for (int rep = 0; rep < 8; rep++) {
                int chunk = tid + rep * 256;
                int row = chunk >> 4, u = chunk & 15;
                unsigned dsto = row * 256 + (((u ^ (row & 7)) << 4));
                size_t srco = (size_t)((kb + 1) * 128 + row) * KVDIM + kvh * HD + u * 8;
                CP_ASYNC16(nb + OF_K + dsto, K16 + srco);
                CP_ASYNC16(nb + OF_V + dsto, V16 + srco);
            }
            CP_COMMIT();
        }

        // ---- S = Q K^T over 128 keys ----
        float S[16][4];
#pragma unroll
        for (int i = 0; i < 16; i++)
#pragma unroll
            for (int c = 0; c < 4; c++) S[i][c] = 0.f;

#pragma unroll
        for (int kc = 0; kc < 8; kc++) {
#pragma unroll
            for (int ntp = 0; ntp < 8; ntp++) {
                int boff = swz(ntp*16 + (lane & 15), kc*16 + (lane >> 4) * 8);
                unsigned k0,k1,k2,k3;
                LDSM_X4(k0,k1,k2,k3, kvb + OF_K + boff);
                MMA16816H(S[2*ntp],   qf[kc][0],qf[kc][1],qf[kc][2],qf[kc][3], k0,k2);
                MMA16816H(S[2*ntp+1], qf[kc][0],qf[kc][1],qf[kc][2],qf[kc][3], k1,k3);
            }
        }

        // ---- mask (only boundary blocks) ----
        bool need_mask = (kb == qb) || (kb == qb - 16);
        if (need_mask) {
#pragma unroll
            for (int nt = 0; nt < 16; nt++) {
                int j0 = kb*128 + nt*8 + 2*qd;
                S[nt][0] = ((unsigned)(ig0 - j0)     <= (unsigned)WIN) ? S[nt][0] : -1e30f;
                S[nt][1] = ((unsigned)(ig0 - j0 - 1) <= (unsigned)WIN) ? S[nt][1] : -1e30f;
                S[nt][2] = ((unsigned)(ig1 - j0)     <= (unsigned)WIN) ? S[nt][2] : -1e30f;
                S[nt][3] = ((unsigned)(ig1 - j0 - 1) <= (unsigned)WIN) ? S[nt][3] : -1e30f;
            }
        }

        // ---- online softmax ----
        float mx0 = -1e30f, mx1 = -1e30f;
#pragma unroll
        for (int nt = 0; nt < 16; nt++) {
            mx0 = fmaxf(mx0, fmaxf(S[nt][0], S[nt][1]));
            mx1 = fmaxf(mx1, fmaxf(S[nt][2], S[nt][3]));
        }
        mx0 = fmaxf(mx0, __shfl_xor_sync(0xffffffffu, mx0, 1));
        mx0 = fmaxf(mx0, __shfl_xor_sync(0xffffffffu, mx0, 2));
        mx1 = fmaxf(mx1, __shfl_xor_sync(0xffffffffu, mx1, 1));
        mx1 = fmaxf(mx1, __shfl_xor_sync(0xffffffffu, mx1, 2));

        float mn0 = fmaxf(m0, mx0);
        float mn1 = fmaxf(m1, mx1);
        float a0 = exp2f(m0 - mn0);
        float a1 = exp2f(m1 - mn1);
        m0 = mn0; m1 = mn1;
        l0s *= a0; l1s *= a1;

#pragma unroll
        for (int nt = 0; nt < 16; nt++) {
            S[nt][0] = exp2f(S[nt][0] - mn0);
            S[nt][1] = exp2f(S[nt][1] - mn0);
            S[nt][2] = exp2f(S[nt][2] - mn1);
            S[nt][3] = exp2f(S[nt][3] - mn1);
            l0s += S[nt][0] + S[nt][1];
            l1s += S[nt][2] + S[nt][3];
        }

        // ---- rescale o only when the running max changed ----
        bool skip = __all_sync(0xffffffffu, (a0 == 1.f) && (a1 == 1.f));
        if (!skip) {
#pragma unroll
            for (int i = 0; i < 16; i++) {
                o[i][0] *= a0; o[i][1] *= a0;
                o[i][2] *= a1; o[i][3] *= a1;
            }
        }

        // ---- pack P (fp16 A-frags) ----
        unsigned ph[8][4];
#pragma unroll
        for (int t = 0; t < 8; t++) {
            ph[t][0] = packh2(S[2*t][0],   S[2*t][1]);
            ph[t][1] = packh2(S[2*t][2],   S[2*t][3]);
            ph[t][2] = packh2(S[2*t+1][0], S[2*t+1][1]);
            ph[t][3] = packh2(S[2*t+1][2], S[2*t+1][3]);
        }

        // ---- O += P V ----
#pragma unroll
        for (int t = 0; t < 8; t++) {
#pragma unroll
            for (int ntp = 0; ntp < 8; ntp++) {
                int voff = swz(t*16 + (lane & 15), ntp*16 + (lane >> 4) * 8);
                unsigned v0,v1,v2,v3;
                LDSM_X4_T(v0,v1,v2,v3, kvb + OF_V + voff);
                MMA16816H(o[2*ntp],   ph[t][0],ph[t][1],ph[t][2],ph[t][3], v0,v1);
                MMA16816H(o[2*ntp+1], ph[t][0],ph[t][1],ph[t][2],ph[t][3], v2,v3);
            }
        }
    }

    l0s += __shfl_xor_sync(0xffffffffu, l0s, 1);
    l0s += __shfl_xor_sync(0xffffffffu, l0s, 2);
    l1s += __shfl_xor_sync(0xffffffffu, l1s, 1);
    l1s += __shfl_xor_sync(0xffffffffu, l1s, 2);
    float inv0 = 1.f / l0s;
    float inv1 = 1.f / l1s;

#pragma unroll
    for (int nt = 0; nt < 16; nt++) {
        int col = h * HD + nt * 8 + 2 * qd;
        *(unsigned*)&O16[(size_t)ig0 * QDIM + col] = packh2(o[nt][0] * inv0, o[nt][1] * inv0);
        *(unsigned*)&O16[(size_t)ig1 * QDIM + col] = packh2(o[nt][2] * inv1, o[nt][3] * inv1);
    }
}

// =====================================================================
extern "C" void kernel_launch(void* const* d_in, const int* in_sizes, int n_in,
                              void* d_out, int out_size)
{
    const float* query = (const float*)d_in[0];
    const float* key   = (const float*)d_in[1];
    const float* value = (const float*)d_in[2];
    const int*   pos   = (const int*)d_in[3];
    const float* wq    = (const float*)d_in[4];
    const float* wk    = (const float*)d_in[5];
    const float* wv    = (const float*)d_in[6];
    const float* wo    = (const float*)d_in[7];
    float*       out   = (float*)d_out;

    float *q_s, *k_s;
    __half *q16,*k16,*v16,*at16,*x16q,*x16k,*x16v;
    __half *w16q,*w16k,*w16v,*w16o;
    cudaGetSymbolAddress((void**)&q_s, g_q);     cudaGetSymbolAddress((void**)&k_s, g_k);
    cudaGetSymbolAddress((void**)&q16, g_q16);   cudaGetSymbolAddress((void**)&k16, g_k16);
    cudaGetSymbolAddress((void**)&v16, g_v16);   cudaGetSymbolAddress((void**)&at16, g_at16);
    cudaGetSymbolAddress((void**)&x16q, g_x16q); cudaGetSymbolAddress((void**)&x16k, g_x16k);
    cudaGetSymbolAddress((void**)&x16v, g_x16v);
    cudaGetSymbolAddress((void**)&w16q, g_w16q); cudaGetSymbolAddress((void**)&w16k, g_w16k);
    cudaGetSymbolAddress((void**)&w16v, g_w16v); cudaGetSymbolAddress((void**)&w16o, g_w16o);

    cudaFuncSetAttribute(attn_mma6, cudaFuncAttributeMaxDynamicSharedMemorySize, SMEM_ATTN6);
    cudaFuncSetAttribute(gemm10,    cudaFuncAttributeMaxDynamicSharedMemorySize, SMEM_G9);

    dim3 blk(256);

    // ---- merged quantize pre-pass (1 launch, 7 tensors) ----
    QPack sp;
    auto mk = [&](const float* s, __half* d, size_t n) {
        return QArg{ (const float4*)s, (uint2*)d, (int)(n / 4 / 256) };
    };
    sp.a[0] = mk(query, x16q, (size_t)SEQ * EMB);
    sp.a[1] = mk(key,   x16k, (size_t)SEQ * EMB);
    sp.a[2] = mk(value, x16v, (size_t)SEQ * EMB);
    sp.a[3] = mk(wq, w16q, (size_t)EMB * QDIM);
    sp.a[4] = mk(wk, w16k, (size_t)EMB * KVDIM);
    sp.a[5] = mk(wv, w16v, (size_t)EMB * KVDIM);
    sp.a[6] = mk(wo, w16o, (size_t)QDIM * EMB);
    int total_blk = 0;
    for (int i = 0; i < 7; i++) total_blk += sp.a[i].nblk;
    quant_all<<<total_blk, blk>>>(sp);

    // ---- q/k/v projections, one launch ----
    GArg gq = { x16q, w16q, q_s, nullptr, QDIM };
    GArg gk = { x16k, w16k, k_s, nullptr, KVDIM };
    GArg gv = { x16v, w16v, nullptr, v16, KVDIM };
    gemm10<<<dim3(24, SEQ/128), blk, SMEM_G9>>>(gq, gk, gv, 16, 20, EMB);

    // ---- rope -> fp16 q/k ----
    rope3_kernel<<<SEQ, blk>>>(pos, q_s, k_s, q16, k16);

    // ---- attention ----
    attn_mma6<<<dim3(SEQ/128, NH), blk, SMEM_ATTN6>>>(q16, k16, v16, at16);

    // ---- output projection ----
    GArg go = { at16, w16o, out, nullptr, EMB };
    gemm10<<<dim3(16, SEQ/128), blk, SMEM_G9>>>(go, go, go, 16, 16, QDIM);
}

// round 17
// speedup vs baseline: 1.0220x; 1.0220x over previous
#include <cuda_runtime.h>
#include <cuda_fp16.h>
#include <math.h>

#define SEQ  4096
#define EMB  2048
#define NH   16
#define NKVH 4
#define HD   128
#define WIN  2048
#define QDIM (NH*HD)    /* 2048 */
#define KVDIM (NKVH*HD) /* 512  */

// -------- scratch (device globals; no allocations allowed) --------
__device__ float  g_q [SEQ * QDIM];
__device__ float  g_k [SEQ * KVDIM];
__device__ __half g_q16[SEQ*QDIM];
__device__ __half g_k16[SEQ*KVDIM];
__device__ __half g_v16[SEQ*KVDIM];
__device__ __half g_at16[SEQ*QDIM];
__device__ __half g_x16q[SEQ*EMB], g_x16k[SEQ*EMB], g_x16v[SEQ*EMB];
__device__ __half g_w16q[EMB*QDIM], g_w16k[EMB*KVDIM], g_w16v[EMB*KVDIM], g_w16o[QDIM*EMB];

// ---------------- PTX helpers ----------------
#define LDSM_X4(r0,r1,r2,r3,addr) \
  asm volatile("ldmatrix.sync.aligned.m8n8.x4.shared.b16 {%0,%1,%2,%3}, [%4];" \
    : "=r"(r0),"=r"(r1),"=r"(r2),"=r"(r3) : "r"(addr))

#define LDSM_X4_T(r0,r1,r2,r3,addr) \
  asm volatile("ldmatrix.sync.aligned.m8n8.x4.trans.shared.b16 {%0,%1,%2,%3}, [%4];" \
    : "=r"(r0),"=r"(r1),"=r"(r2),"=r"(r3) : "r"(addr))

#define MMA16816H(c, a0,a1,a2,a3, b0,b1) \
  asm volatile("mma.sync.aligned.m16n8k16.row.col.f32.f16.f16.f32 " \
    "{%0,%1,%2,%3}, {%4,%5,%6,%7}, {%8,%9}, {%0,%1,%2,%3};" \
    : "+f"((c)[0]),"+f"((c)[1]),"+f"((c)[2]),"+f"((c)[3]) \
    : "r"(a0),"r"(a1),"r"(a2),"r"(a3),"r"(b0),"r"(b1))

#define CP_ASYNC16(dst32, srcptr) \
  asm volatile("cp.async.cg.shared.global [%0], [%1], 16;" :: "r"(dst32), "l"(srcptr))
#define CP_COMMIT() asm volatile("cp.async.commit_group;")
#define CP_WAIT0()  asm volatile("cp.async.wait_group 0;")
#define CP_WAIT1()  asm volatile("cp.async.wait_group 1;")

__device__ __forceinline__ unsigned packh2(float a, float b) {
    __half2 h = __floats2half2_rn(a, b);
    return *(unsigned*)&h;
}

// =====================================================================
// merged pre-pass: quantize all 7 tensors to fp16 (1 launch)
// =====================================================================
struct QArg { const float4* s; uint2* d; int nblk; };
struct QPack { QArg a[7]; };

__global__ __launch_bounds__(256) void quant_all(QPack p)
{
    int b = blockIdx.x;
    int seg = 0;
#pragma unroll
    for (int i = 0; i < 7; i++) {
        if (b >= p.a[seg].nblk) { b -= p.a[seg].nblk; seg++; }
    }
    const QArg sa = p.a[seg];
    int i = b * 256 + threadIdx.x;
    float4 v = sa.s[i];
    sa.d[i] = make_uint2(packh2(v.x, v.y), packh2(v.z, v.w));
}

// =====================================================================
// fp16 GEMM v11: 1 MMA/product, BK=64, 3-stage cp.async (wait_group 1),
// CTA 128x128, warp 64x32, 105KB smem -> 2 CTAs/SM.
// =====================================================================
#define A9_STRIDE 72
#define B9_STRIDE 136
#define G9_A  0
#define G9_B  18432
#define G9_STAGE 35840
#define SMEM_G11 (3*G9_STAGE)   /* 107520 */

struct GArg {
    const __half *A, *B;
    float* C;
    __half* C16;
    int N;
};

__global__ __launch_bounds__(256, 2) void gemm11(
    GArg a0, GArg a1, GArg a2, int t0, int t1, int K)
{
    extern __shared__ char smg[];
    const unsigned smu = (unsigned)__cvta_generic_to_shared(smg);

    GArg ga; int bx = blockIdx.x, bn;
    if (bx < t0)      { ga = a0; bn = bx * 128; }
    else if (bx < t1) { ga = a1; bn = (bx - t0) * 128; }
    else              { ga = a2; bn = (bx - t1) * 128; }
    const int N  = ga.N;
    const int bm = blockIdx.y * 128;

    const int tid  = threadIdx.x;
    const int warp = tid >> 5;
    const int lane = tid & 31;
    const int wm   = warp >> 2;
    const int wn   = warp & 3;

    float acc[4][4][4];
#pragma unroll
    for (int i = 0; i < 4; i++)
#pragma unroll
        for (int j = 0; j < 4; j++)
#pragma unroll
            for (int r = 0; r < 4; r++) acc[i][j][r] = 0.f;

    auto issue = [&](int stage, int k0) {
        unsigned sb = smu + stage * G9_STAGE;
#pragma unroll
        for (int p = 0; p < 4; p++) {
            int idx = tid + p * 256;
            int row = idx >> 3, u = idx & 7;
            CP_ASYNC16(sb + G9_A + row*144 + u*16, ga.A + (size_t)(bm + row)*K + k0 + u*8);
        }
#pragma unroll
        for (int p = 0; p < 4; p++) {
            int idx = tid + p * 256;
            int row = idx >> 4, u = idx & 15;
            CP_ASYNC16(sb + G9_B + row*272 + u*16, ga.B + (size_t)(k0 + row)*N + bn + u*8);
        }
        CP_COMMIT();
    };

    issue(0, 0);
    issue(1, 64);

    const int a_lrow = wm*64 + (lane & 15);
    const int a_lcol = (lane >> 4) * 8;

    const int nch = K / 64;
    for (int j = 0; j < nch; j++) {
        if (j == nch - 1) { CP_WAIT0(); } else { CP_WAIT1(); }
        __syncthreads();
        if (j + 2 < nch) issue((j + 2) % 3, (j + 2) * 64);

        const unsigned sa = smu + (j % 3) * G9_STAGE;

#pragma unroll
        for (int ks = 0; ks < 64; ks += 16) {
            unsigned ah[4][4];
#pragma unroll
            for (int mi = 0; mi < 4; mi++) {
                unsigned off = 2u * ((unsigned)((a_lrow + mi*16) * A9_STRIDE + ks + a_lcol));
                LDSM_X4(ah[mi][0], ah[mi][1], ah[mi][2], ah[mi][3], sa + G9_A + off);
            }
            unsigned bh[4][2];
#pragma unroll
            for (int nb = 0; nb < 2; nb++) {
                unsigned off = 2u * ((unsigned)((ks + (lane & 15)) * B9_STRIDE
                                               + wn*32 + nb*16 + (lane >> 4) * 8));
                unsigned r0, r1, r2, r3;
                LDSM_X4_T(r0, r1, r2, r3, sa + G9_B + off);
                bh[2*nb][0] = r0; bh[2*nb][1] = r1;
                bh[2*nb+1][0] = r2; bh[2*nb+1][1] = r3;
            }
#pragma unroll
            for (int mi = 0; mi < 4; mi++) {
#pragma unroll
                for (int ni = 0; ni < 4; ni++) {
                    MMA16816H(acc[mi][ni], ah[mi][0],ah[mi][1],ah[mi][2],ah[mi][3],
                              bh[ni][0], bh[ni][1]);
                }
            }
        }
    }

    const int g = lane >> 2, q = lane & 3;
#pragma unroll
    for (int mi = 0; mi < 4; mi++) {
#pragma unroll
        for (int ni = 0; ni < 4; ni++) {
            int row = bm + wm*64 + mi*16 + g;
            int col = bn + wn*32 + ni*8 + q*2;
            if (ga.C) {
                *(float2*)&ga.C[(size_t)row * N + col]       = make_float2(acc[mi][ni][0], acc[mi][ni][1]);
                *(float2*)&ga.C[(size_t)(row + 8) * N + col] = make_float2(acc[mi][ni][2], acc[mi][ni][3]);
            }
            if (ga.C16) {
                *(unsigned*)&ga.C16[(size_t)row * N + col]       = packh2(acc[mi][ni][0], acc[mi][ni][1]);
                *(unsigned*)&ga.C16[(size_t)(row + 8) * N + col] = packh2(acc[mi][ni][2], acc[mi][ni][3]);
            }
        }
    }
}

// =====================================================================
// RoPE (unchanged)
// =====================================================================
__global__ __launch_bounds__(256) void rope3_kernel(
    const int* __restrict__ pos_w,
    const float* __restrict__ q, const float* __restrict__ k,
    __half* __restrict__ q16, __half* __restrict__ k16)
{
    const int s = blockIdx.x;
    const int tid = threadIdx.x;
    __shared__ float cs[64], sn[64];

    const float QSCALE = (float)(1.4426950408889634 * 0.08838834764831845);

    if (tid < 64) {
        bool is64 = (pos_w[1] == 0);
        int pi = is64 ? pos_w[2 * s] : pos_w[s];
        float p = (float)pi;
        float ex = (float)(2 * tid) / (float)HD;
        float inv = powf(10000.0f, -ex);
        float ang = p * inv;
        sincosf(ang, &sn[tid], &cs[tid]);
    }
    __syncthreads();

    for (int idx = tid; idx < NH * 64; idx += 256) {
        int h = idx >> 6, d = idx & 63;
        size_t base = (size_t)s * QDIM + h * HD;
        float x1 = q[base + d], x2 = q[base + d + 64];
        float c = cs[d], si = sn[d];
        q16[base + d]      = __float2half_rn((x1 * c - x2 * si) * QSCALE);
        q16[base + d + 64] = __float2half_rn((x2 * c + x1 * si) * QSCALE);
    }
    for (int idx = tid; idx < NKVH * 64; idx += 256) {
        int h = idx >> 6, d = idx & 63;
        size_t base = (size_t)s * KVDIM + h * HD;
        float x1 = k[base + d], x2 = k[base + d + 64];
        float c = cs[d], si = sn[d];
        k16[base + d]      = __float2half_rn(x1 * c - x2 * si);
        k16[base + d + 64] = __float2half_rn(x2 * c + x1 * si);
    }
}

// =====================================================================
// MMA flash attention v7 = R15's v5 structure, with ONLY the dead
// ok0/ok1 multiplies removed (bit-identical: every row's first in-window
// block has >=1 valid key, so the running max is finite from block one).
// smem: Q 32KB + 2 x (K 32KB + V 32KB) = 160KB.
// =====================================================================
#define SMQ    0
#define KVBUF0 32768
#define KVSZ   65536
#define OF_K   0
#define OF_V   32768
#define SMEM_ATTN7 163840

__device__ __forceinline__ int swz(int row, int col_b16) {
    return row * 256 + ((((col_b16 >> 3) ^ (row & 7)) << 4)) + ((col_b16 & 7) << 1);
}

__global__ __launch_bounds__(256) void attn_mma7(
    const __half* __restrict__ Q16, const __half* __restrict__ K16,
    const __half* __restrict__ V16, __half* __restrict__ O16)
{
    extern __shared__ char sm[];
    const unsigned smu = (unsigned)__cvta_generic_to_shared(sm);

    const int tid  = threadIdx.x;
    const int warp = tid >> 5;
    const int lane = tid & 31;
    const int g    = lane >> 2;
    const int qd   = lane & 3;
    const int qb   = blockIdx.x;
    const int h    = blockIdx.y;
    const int kvh  = h >> 2;
    const int i0   = qb * 128;

    const int kb_lo = max(0, qb - 16);
    const int kb_hi = qb;

    {
#pragma unroll
        for (int rep = 0; rep < 8; rep++) {
            int chunk = tid + rep * 256;
            int row = chunk >> 4, u = chunk & 15;
            unsigned dsto = row * 256 + (((u ^ (row & 7)) << 4));
            CP_ASYNC16(smu + SMQ + dsto, Q16 + (size_t)(i0 + row) * QDIM + h * HD + u * 8);
        }
#pragma unroll
        for (int rep = 0; rep < 8; rep++) {
            int chunk = tid + rep * 256;
            int row = chunk >> 4, u = chunk & 15;
            unsigned dsto = row * 256 + (((u ^ (row & 7)) << 4));
            size_t srco = (size_t)(kb_lo * 128 + row) * KVDIM + kvh * HD + u * 8;
            CP_ASYNC16(smu + KVBUF0 + OF_K + dsto, K16 + srco);
            CP_ASYNC16(smu + KVBUF0 + OF_V + dsto, V16 + srco);
        }
        CP_COMMIT();
    }

    float o[16][4];
#pragma unroll
    for (int i = 0; i < 16; i++)
#pragma unroll
        for (int c = 0; c < 4; c++) o[i][c] = 0.f;

    float m0 = -1e30f, m1 = -1e30f, l0s = 0.f, l1s = 0.f;

    const int ig0 = i0 + warp * 16 + g;
    const int ig1 = ig0 + 8;

    for (int kb = kb_lo; kb <= kb_hi; kb++) {
        CP_WAIT0();
        __syncthreads();

        const int buf = (kb - kb_lo) & 1;
        const unsigned kvb = smu + KVBUF0 + buf * KVSZ;

        if (kb + 1 <= kb_hi) {
            const unsigned nb = smu + KVBUF0 + (buf ^ 1) * KVSZ;
#pragma unroll
            for (int rep = 0; rep < 8; rep++) {
                int chunk = tid + rep * 256;
                int row = chunk >> 4, u = chunk & 15;
                unsigned dsto = row * 256 + (((u ^ (row & 7)) << 4));
                size_t srco = (size_t)((kb + 1) * 128 + row) * KVDIM + kvh * HD + u * 8;
                CP_ASYNC16(nb + OF_K + dsto, K16 + srco);
                CP_ASYNC16(nb + OF_V + dsto, V16 + srco);
            }
            CP_COMMIT();
        }

        // ---- S = Q K^T over 128 keys ----
        float S[16][4];
#pragma unroll
        for (int i = 0; i < 16; i++)
#pragma unroll
            for (int c = 0; c < 4; c++) S[i][c] = 0.f;

#pragma unroll
        for (int kc = 0; kc < 8; kc++) {
            unsigned a0,a1,a2,a3;
            {
                int aoff = swz(warp*16 + (lane & 15), kc*16 + (lane >> 4) * 8);
                LDSM_X4(a0,a1,a2,a3, smu + SMQ + aoff);
            }
#pragma unroll
            for (int ntp = 0; ntp < 8; ntp++) {
                int boff = swz(ntp*16 + (lane & 15), kc*16 + (lane >> 4) * 8);
                unsigned k0,k1,k2,k3;
                LDSM_X4(k0,k1,k2,k3, kvb + OF_K + boff);
                MMA16816H(S[2*ntp],   a0,a1,a2,a3, k0,k2);
                MMA16816H(S[2*ntp+1], a0,a1,a2,a3, k1,k3);
            }
        }

        // ---- mask (only boundary blocks) ----
        bool need_mask = (kb == qb) || (kb == qb - 16);
        if (need_mask) {
#pragma unroll
            for (int nt = 0; nt < 16; nt++) {
                int j0 = kb*128 + nt*8 + 2*qd;
                S[nt][0] = ((unsigned)(ig0 - j0)     <= (unsigned)WIN) ? S[nt][0] : -1e30f;
                S[nt][1] = ((unsigned)(ig0 - j0 - 1) <= (unsigned)WIN) ? S[nt][1] : -1e30f;
                S[nt][2] = ((unsigned)(ig1 - j0)     <= (unsigned)WIN) ? S[nt][2] : -1e30f;
                S[nt][3] = ((unsigned)(ig1 - j0 - 1) <= (unsigned)WIN) ? S[nt][3] : -1e30f;
            }
        }

        // ---- online softmax ----
        float mx0 = -1e30f, mx1 = -1e30f;
#pragma unroll
        for (int nt = 0; nt < 16; nt++) {
            mx0 = fmaxf(mx0, fmaxf(S[nt][0], S[nt][1]));
            mx1 = fmaxf(mx1, fmaxf(S[nt][2], S[nt][3]));
        }
        mx0 = fmaxf(mx0, __shfl_xor_sync(0xffffffffu, mx0, 1));
        mx0 = fmaxf(mx0, __shfl_xor_sync(0xffffffffu, mx0, 2));
        mx1 = fmaxf(mx1, __shfl_xor_sync(0xffffffffu, mx1, 1));
        mx1 = fmaxf(mx1, __shfl_xor_sync(0xffffffffu, mx1, 2));

        float mn0 = fmaxf(m0, mx0);
        float mn1 = fmaxf(m1, mx1);
        float a0 = exp2f(m0 - mn0);
        float a1 = exp2f(m1 - mn1);
        m0 = mn0; m1 = mn1;
        l0s *= a0; l1s *= a1;

#pragma unroll
        for (int nt = 0; nt < 16; nt++) {
            S[nt][0] = exp2f(S[nt][0] - mn0);
            S[nt][1] = exp2f(S[nt][1] - mn0);
            S[nt][2] = exp2f(S[nt][2] - mn1);
            S[nt][3] = exp2f(S[nt][3] - mn1);
            l0s += S[nt][0] + S[nt][1];
            l1s += S[nt][2] + S[nt][3];
        }

#pragma unroll
        for (int i = 0; i < 16; i++) {
            o[i][0] *= a0; o[i][1] *= a0;
            o[i][2] *= a1; o[i][3] *= a1;
        }

        // ---- pack P (fp16 A-frags), 8 key-chunks ----
        unsigned ph[8][4];
#pragma unroll
        for (int t = 0; t < 8; t++) {
            ph[t][0] = packh2(S[2*t][0],   S[2*t][1]);
            ph[t][1] = packh2(S[2*t][2],   S[2*t][3]);
            ph[t][2] = packh2(S[2*t+1][0], S[2*t+1][1]);
            ph[t][3] = packh2(S[2*t+1][2], S[2*t+1][3]);
        }

        // ---- O += P V ----
#pragma unroll
        for (int t = 0; t < 8; t++) {
#pragma unroll
            for (int ntp = 0; ntp < 8; ntp++) {
                int voff = swz(t*16 + (lane & 15), ntp*16 + (lane >> 4) * 8);
                unsigned v0,v1,v2,v3;
                LDSM_X4_T(v0,v1,v2,v3, kvb + OF_V + voff);
                MMA16816H(o[2*ntp],   ph[t][0],ph[t][1],ph[t][2],ph[t][3], v0,v1);
                MMA16816H(o[2*ntp+1], ph[t][0],ph[t][1],ph[t][2],ph[t][3], v2,v3);
            }
        }
    }

    l0s += __shfl_xor_sync(0xffffffffu, l0s, 1);
    l0s += __shfl_xor_sync(0xffffffffu, l0s, 2);
    l1s += __shfl_xor_sync(0xffffffffu, l1s, 1);
    l1s += __shfl_xor_sync(0xffffffffu, l1s, 2);
    float inv0 = 1.f / l0s;
    float inv1 = 1.f / l1s;

#pragma unroll
    for (int nt = 0; nt < 16; nt++) {
        int col = h * HD + nt * 8 + 2 * qd;
        *(unsigned*)&O16[(size_t)ig0 * QDIM + col] = packh2(o[nt][0] * inv0, o[nt][1] * inv0);
        *(unsigned*)&O16[(size_t)ig1 * QDIM + col] = packh2(o[nt][2] * inv1, o[nt][3] * inv1);
    }
}

// =====================================================================
extern "C" void kernel_launch(void* const* d_in, const int* in_sizes, int n_in,
                              void* d_out, int out_size)
{
    const float* query = (const float*)d_in[0];
    const float* key   = (const float*)d_in[1];
    const float* value = (const float*)d_in[2];
    const int*   pos   = (const int*)d_in[3];
    const float* wq    = (const float*)d_in[4];
    const float* wk    = (const float*)d_in[5];
    const float* wv    = (const float*)d_in[6];
    const float* wo    = (const float*)d_in[7];
    float*       out   = (float*)d_out;

    float *q_s, *k_s;
    __half *q16,*k16,*v16,*at16,*x16q,*x16k,*x16v;
    __half *w16q,*w16k,*w16v,*w16o;
    cudaGetSymbolAddress((void**)&q_s, g_q);     cudaGetSymbolAddress((void**)&k_s, g_k);
    cudaGetSymbolAddress((void**)&q16, g_q16);   cudaGetSymbolAddress((void**)&k16, g_k16);
    cudaGetSymbolAddress((void**)&v16, g_v16);   cudaGetSymbolAddress((void**)&at16, g_at16);
    cudaGetSymbolAddress((void**)&x16q, g_x16q); cudaGetSymbolAddress((void**)&x16k, g_x16k);
    cudaGetSymbolAddress((void**)&x16v, g_x16v);
    cudaGetSymbolAddress((void**)&w16q, g_w16q); cudaGetSymbolAddress((void**)&w16k, g_w16k);
    cudaGetSymbolAddress((void**)&w16v, g_w16v); cudaGetSymbolAddress((void**)&w16o, g_w16o);

    cudaFuncSetAttribute(attn_mma7, cudaFuncAttributeMaxDynamicSharedMemorySize, SMEM_ATTN7);
    cudaFuncSetAttribute(gemm11,    cudaFuncAttributeMaxDynamicSharedMemorySize, SMEM_G11);

    dim3 blk(256);

    // ---- merged quantize pre-pass (1 launch, 7 tensors) ----
    QPack sp;
    auto mk = [&](const float* s, __half* d, size_t n) {
        return QArg{ (const float4*)s, (uint2*)d, (int)(n / 4 / 256) };
    };
    sp.a[0] = mk(query, x16q, (size_t)SEQ * EMB);
    sp.a[1] = mk(key,   x16k, (size_t)SEQ * EMB);
    sp.a[2] = mk(value, x16v, (size_t)SEQ * EMB);
    sp.a[3] = mk(wq, w16q, (size_t)EMB * QDIM);
    sp.a[4] = mk(wk, w16k, (size_t)EMB * KVDIM);
    sp.a[5] = mk(wv, w16v, (size_t)EMB * KVDIM);
    sp.a[6] = mk(wo, w16o, (size_t)QDIM * EMB);
    int total_blk = 0;
    for (int i = 0; i < 7; i++) total_blk += sp.a[i].nblk;
    quant_all<<<total_blk, blk>>>(sp);

    // ---- q/k/v projections, one launch ----
    GArg gq = { x16q, w16q, q_s, nullptr, QDIM };
    GArg gk = { x16k, w16k, k_s, nullptr, KVDIM };
    GArg gv = { x16v, w16v, nullptr, v16, KVDIM };
    gemm11<<<dim3(24, SEQ/128), blk, SMEM_G11>>>(gq, gk, gv, 16, 20, EMB);

    // ---- rope -> fp16 q/k ----
    rope3_kernel<<<SEQ, blk>>>(pos, q_s, k_s, q16, k16);

    // ---- attention ----
    attn_mma7<<<dim3(SEQ/128, NH), blk, SMEM_ATTN7>>>(q16, k16, v16, at16);

    // ---- output projection ----
    GArg go = { at16, w16o, out, nullptr, EMB };
    gemm11<<<dim3(16, SEQ/128), blk, SMEM_G11>>>(go, go, go, 16, 16, QDIM);
}